// round 8
// baseline (speedup 1.0000x reference)
#include <cuda_runtime.h>
#include <math.h>

#define BB   4
#define SSS  12
#define NP   512
#define DD   128
#define HH   8
#define HDp  16
#define MTOT (BB*SSS*NP)   /* 24576 */

// ---------------- scratch (static device arrays; no allocs allowed) ----------
__device__ float g_q [MTOT*DD];
__device__ float g_k [MTOT*DD];
__device__ float g_v [MTOT*DD];
__device__ float g_ao[MTOT*DD];
__device__ unsigned char g_mask[BB*NP*NP];

__constant__ float c_ql[19] = {0.01f,0.1f,0.11f,0.2f,0.21f,0.3f,0.31f,0.4f,0.41f,
                               0.5f,0.51f,0.6f,0.61f,0.7f,0.71f,0.8f,0.81f,0.9f,0.91f};

// fp32 congestion threshold (JAX weak-types the python float literal to f32)
#define CONGEST_F32 ((float)-0.2260138304488262)

// XLA GPU row-reduction order for a 12-row: 16-lane shuffle tree, zero-padded.
// lanes j<12 hold e_j; off8,4,2,1 butterfly =>
//   m0=(e0+e8)+e4  m1=(e1+e9)+e5  m2=(e2+e10)+e6  m3=(e3+e11)+e7
//   result = (m0+m2) + (m1+m3)          (adds of the 0-pads are exact no-ops)
__device__ __forceinline__ float xla_tree12(const float* e) {
    float m0 = __fadd_rn(__fadd_rn(e[0], e[8]),  e[4]);
    float m1 = __fadd_rn(__fadd_rn(e[1], e[9]),  e[5]);
    float m2 = __fadd_rn(__fadd_rn(e[2], e[10]), e[6]);
    float m3 = __fadd_rn(__fadd_rn(e[3], e[11]), e[7]);
    return __fadd_rn(__fadd_rn(m0, m2), __fadd_rn(m1, m3));
}

// ---------------------------------------------------------------------------
// Mask kernel: one block per (b, n). 512 threads. tree16 reduces; quantile
// interp matches NVPTX FMA contraction: fma(lo, lw, rn(hi*hw)).
// ---------------------------------------------------------------------------
__global__ __launch_bounds__(512) void mask_kernel(const float* __restrict__ x,
                                                   unsigned char* __restrict__ mask) {
    __shared__ float xn[12];
    __shared__ float ss[512];
    __shared__ float sq[19];
    const int n = blockIdx.x, b = blockIdx.y;
    const int t = threadIdx.x;

    if (t < 12) xn[t] = x[(b*NP + n)*12 + t];
    __syncthreads();

    float ad[12], xv[12];
    #pragma unroll
    for (int s2 = 0; s2 < 12; s2++) {
        float xm = x[(b*NP + t)*12 + s2];
        xv[s2] = xm;
        ad[s2] = fabsf(__fadd_rn(xn[s2], -xm));
    }
    const float dist  = xla_tree12(ad);
    const float xmean = __fdiv_rn(xla_tree12(xv), 12.0f);
    ss[t] = dist;
    __syncthreads();

    // bitonic sort ascending, 512 keys (exact; no fp-order sensitivity)
    for (int k = 2; k <= 512; k <<= 1) {
        for (int j = k >> 1; j > 0; j >>= 1) {
            int ixj = t ^ j;
            if (ixj > t) {
                float a = ss[t], c = ss[ixj];
                bool up = ((t & k) == 0);
                if ((a > c) == up) { ss[t] = c; ss[ixj] = a; }
            }
            __syncthreads();
        }
    }

    if (t < 19) {
        float hpos = __fmul_rn(c_ql[t], 511.0f);   // q * (n-1), f32
        float lo   = floorf(hpos);
        float hw   = __fadd_rn(hpos, -lo);
        float lw   = __fadd_rn(1.0f, -hw);
        int   il   = (int)lo;
        // add(mul(lo,lw), mul(hi,hw)) contracted by NVPTX: fma on FIRST mul
        sq[t] = __fmaf_rn(ss[il], lw, __fmul_rn(ss[il+1], hw));
    }
    __syncthreads();

    bool msk = (dist <= sq[0]);
    #pragma unroll
    for (int bnd = 0; bnd < 9; bnd++)
        msk = msk || (dist >= sq[1 + 2*bnd] && dist <= sq[2 + 2*bnd]);
    msk = msk || (xmean <= CONGEST_F32);           // strict, f32 vs f32

    mask[((size_t)b*NP + n)*NP + t] = msk ? (unsigned char)1 : (unsigned char)0;
}

// ---------------------------------------------------------------------------
// C[M x 128] = A[M x 128] @ W^T + bias, plain fp32 tiled SGEMM (64x64x16)
// ---------------------------------------------------------------------------
__global__ __launch_bounds__(256) void gemm_nt_bias(const float* __restrict__ A,
                                                    const float* __restrict__ W,
                                                    const float* __restrict__ bias,
                                                    float* __restrict__ C) {
    __shared__ float As[64][17];
    __shared__ float Ws[64][17];
    const int bm = blockIdx.x * 64;
    const int bn = blockIdx.y * 64;
    const int tid = threadIdx.x;
    const int tx4 = (tid & 15) * 4, ty4 = (tid >> 4) * 4;

    float acc[4][4] = {};
    for (int k0 = 0; k0 < 128; k0 += 16) {
        #pragma unroll
        for (int l = 0; l < 4; l++) {
            int idx = tid + l*256;
            int row = idx >> 4, kk = idx & 15;
            As[row][kk] = A[(size_t)(bm+row)*128 + k0 + kk];
            Ws[row][kk] = W[(bn+row)*128 + k0 + kk];
        }
        __syncthreads();
        #pragma unroll
        for (int kk = 0; kk < 16; kk++) {
            float a[4], w[4];
            #pragma unroll
            for (int i = 0; i < 4; i++) a[i] = As[ty4+i][kk];
            #pragma unroll
            for (int j = 0; j < 4; j++) w[j] = Ws[tx4+j][kk];
            #pragma unroll
            for (int i = 0; i < 4; i++)
                #pragma unroll
                for (int j = 0; j < 4; j++)
                    acc[i][j] += a[i] * w[j];
        }
        __syncthreads();
    }
    #pragma unroll
    for (int i = 0; i < 4; i++)
        #pragma unroll
        for (int j = 0; j < 4; j++)
            C[(size_t)(bm+ty4+i)*128 + bn+tx4+j] = acc[i][j] + bias[bn+tx4+j];
}

// ---------------------------------------------------------------------------
// Attention: one block per (b,s,h). K/V head slices staged TRANSPOSED in
// 64KB dynamic smem; warp handles 2 queries at a time. Pure fp32.
// ---------------------------------------------------------------------------
__global__ __launch_bounds__(256) void attn_kernel(const float* __restrict__ gq,
                                                   const float* __restrict__ gk,
                                                   const float* __restrict__ gv,
                                                   const unsigned char* __restrict__ gmask,
                                                   float* __restrict__ gout) {
    extern __shared__ float sh[];          // Kt[16][512] | Vt[16][512]
    float* Kt = sh;
    float* Vt = sh + HDp*NP;

    const int blk = blockIdx.x;
    const int h   = blk & (HH-1);
    const int bs  = blk >> 3;              // b*S + s
    const int b   = bs / SSS;

    const float* kbase = gk + (size_t)bs*NP*DD + h*HDp;
    const float* vbase = gv + (size_t)bs*NP*DD + h*HDp;
    const float* qbase = gq + (size_t)bs*NP*DD + h*HDp;
    float*       obase = gout + (size_t)bs*NP*DD + h*HDp;
    const unsigned char* maskb = gmask + (size_t)b*NP*NP;

    const int tid = threadIdx.x;
    for (int i = tid; i < NP*HDp; i += 256) {
        int m = i >> 4, d = i & 15;
        Kt[d*NP + m] = kbase[(size_t)m*DD + d];
        Vt[d*NP + m] = vbase[(size_t)m*DD + d];
    }
    __syncthreads();

    const int warp = tid >> 5, lane = tid & 31;

    for (int it = 0; it < 32; ++it) {
        const int n0 = warp*64 + it*2;     // queries n0, n0+1

        float q0[16], q1[16];
        #pragma unroll
        for (int d = 0; d < 16; d++) {
            q0[d] = qbase[(size_t)n0*DD + d];
            q1[d] = qbase[(size_t)(n0+1)*DD + d];
        }

        const unsigned char* mr0 = maskb + (size_t)n0*NP;
        const unsigned char* mr1 = mr0 + NP;

        float lg0[16], lg1[16];
        #pragma unroll
        for (int i = 0; i < 16; i++) {
            const int m = i*32 + lane;
            float a0 = 0.f, a1 = 0.f;
            #pragma unroll
            for (int d = 0; d < 16; d++) {
                float kv = Kt[d*NP + m];
                a0 += q0[d]*kv;
                a1 += q1[d]*kv;
            }
            lg0[i] = mr0[m] ? a0*0.25f : -INFINITY;
            lg1[i] = mr1[m] ? a1*0.25f : -INFINITY;
        }

        // softmax (warp-wide max/sum)
        float mx0 = -INFINITY, mx1 = -INFINITY;
        #pragma unroll
        for (int i = 0; i < 16; i++) { mx0 = fmaxf(mx0, lg0[i]); mx1 = fmaxf(mx1, lg1[i]); }
        #pragma unroll
        for (int off = 16; off; off >>= 1) {
            mx0 = fmaxf(mx0, __shfl_xor_sync(0xffffffffu, mx0, off));
            mx1 = fmaxf(mx1, __shfl_xor_sync(0xffffffffu, mx1, off));
        }
        float s0 = 0.f, s1 = 0.f;
        #pragma unroll
        for (int i = 0; i < 16; i++) {
            lg0[i] = expf(lg0[i] - mx0);  s0 += lg0[i];
            lg1[i] = expf(lg1[i] - mx1);  s1 += lg1[i];
        }
        #pragma unroll
        for (int off = 16; off; off >>= 1) {
            s0 += __shfl_xor_sync(0xffffffffu, s0, off);
            s1 += __shfl_xor_sync(0xffffffffu, s1, off);
        }

        // PV
        float acc0[16] = {}, acc1[16] = {};
        #pragma unroll
        for (int i = 0; i < 16; i++) {
            const int m = i*32 + lane;
            const float p0 = lg0[i], p1 = lg1[i];
            #pragma unroll
            for (int d = 0; d < 16; d++) {
                float vv = Vt[d*NP + m];
                acc0[d] += p0*vv;
                acc1[d] += p1*vv;
            }
        }
        #pragma unroll
        for (int off = 16; off; off >>= 1)
            #pragma unroll
            for (int d = 0; d < 16; d++) {
                acc0[d] += __shfl_xor_sync(0xffffffffu, acc0[d], off);
                acc1[d] += __shfl_xor_sync(0xffffffffu, acc1[d], off);
            }

        const float inv0 = 1.0f / s0, inv1 = 1.0f / s1;
        float w0 = 0.f, w1 = 0.f;
        #pragma unroll
        for (int d = 0; d < 16; d++)
            if (lane == d) { w0 = acc0[d]; w1 = acc1[d]; }
        if (lane < 16) {
            obase[(size_t)n0*DD + lane]     = w0 * inv0;
            obase[(size_t)(n0+1)*DD + lane] = w1 * inv1;
        }
    }
}

// ---------------------------------------------------------------------------
extern "C" void kernel_launch(void* const* d_in, const int* in_sizes, int n_in,
                              void* d_out, int out_size) {
    const float* query = (const float*)d_in[0];
    const float* key   = (const float*)d_in[1];
    const float* value = (const float*)d_in[2];
    const float* x     = (const float*)d_in[3];
    const float* Wq    = (const float*)d_in[4];
    const float* bq    = (const float*)d_in[5];
    const float* Wk    = (const float*)d_in[6];
    const float* bk    = (const float*)d_in[7];
    const float* Wv    = (const float*)d_in[8];
    const float* bv    = (const float*)d_in[9];
    const float* Wo    = (const float*)d_in[10];
    const float* bo    = (const float*)d_in[11];
    float* out = (float*)d_out;

    float *pq, *pk, *pv, *pao; unsigned char* pmask;
    cudaGetSymbolAddress((void**)&pq,    g_q);
    cudaGetSymbolAddress((void**)&pk,    g_k);
    cudaGetSymbolAddress((void**)&pv,    g_v);
    cudaGetSymbolAddress((void**)&pao,   g_ao);
    cudaGetSymbolAddress((void**)&pmask, g_mask);

    cudaFuncSetAttribute(attn_kernel, cudaFuncAttributeMaxDynamicSharedMemorySize, 65536);

    // 1) LSH mask
    mask_kernel<<<dim3(NP, BB), NP>>>(x, pmask);

    // 2) projections
    dim3 gg(MTOT/64, 2);
    gemm_nt_bias<<<gg, 256>>>(query, Wq, bq, pq);
    gemm_nt_bias<<<gg, 256>>>(key,   Wk, bk, pk);
    gemm_nt_bias<<<gg, 256>>>(value, Wv, bv, pv);

    // 3) attention
    attn_kernel<<<BB*SSS*HH, 256, 65536>>>(pq, pk, pv, pmask, pao);

    // 4) output projection
    gemm_nt_bias<<<gg, 256>>>(pao, Wo, bo, out);
}